// round 1
// baseline (speedup 1.0000x reference)
#include <cuda_runtime.h>
#include <stdint.h>

// Problem constants (preds: [32, 3, 640, 640] fp32)
#define B_    32
#define H_    640
#define W_    640
#define HW_   (H_ * W_)          // 409600
#define TOPK_ 1000
#define NBUCK 4096               // 12-bit radix buckets
#define CAP   4096               // candidate cap per image

// Scratch (no allocations allowed)
__device__ unsigned int       g_hist[B_ * NBUCK];
__device__ int                g_count[B_];
__device__ unsigned int       g_thresh[B_];
__device__ unsigned long long g_cand[B_ * CAP];

// Order-preserving bijection float -> uint (monotone increasing)
__device__ __forceinline__ unsigned int ordf(float x) {
    unsigned int u = __float_as_uint(x);
    return (u & 0x80000000u) ? ~u : (u | 0x80000000u);
}

// ---------------------------------------------------------------------------
// Kernel 0: zero scratch (histograms + counters). Must run every launch
// (graph replays).
// ---------------------------------------------------------------------------
__global__ void k_zero() {
    int i = blockIdx.x * blockDim.x + threadIdx.x;
    if (i < B_ * NBUCK) g_hist[i] = 0u;
    if (i < B_)         g_count[i] = 0;
}

// ---------------------------------------------------------------------------
// Kernel 1: per-image 4096-bucket histogram of score bits.
// grid = (25, 32), block = 256. Each block: 4096 float4 = 16384 scores.
// ---------------------------------------------------------------------------
__global__ void k_hist(const float* __restrict__ preds) {
    __shared__ unsigned int sh[NBUCK];
    const int b = blockIdx.y;
    for (int i = threadIdx.x; i < NBUCK; i += 256) sh[i] = 0u;
    __syncthreads();

    const float4* sc = (const float4*)(preds + (size_t)b * 3 * HW_);
    const int base = blockIdx.x * 4096;  // in float4 units
    for (int i = threadIdx.x; i < 4096; i += 256) {
        float4 v = sc[base + i];
        atomicAdd(&sh[ordf(v.x) >> 20], 1u);
        atomicAdd(&sh[ordf(v.y) >> 20], 1u);
        atomicAdd(&sh[ordf(v.z) >> 20], 1u);
        atomicAdd(&sh[ordf(v.w) >> 20], 1u);
    }
    __syncthreads();

    unsigned int* gh = g_hist + b * NBUCK;
    for (int i = threadIdx.x; i < NBUCK; i += 256)
        if (sh[i]) atomicAdd(&gh[i], sh[i]);
}

// ---------------------------------------------------------------------------
// Kernel 2: per-image suffix scan over buckets -> threshold bucket T
// (largest T with #elements in buckets >= T  >= TOPK).
// grid = 32 blocks, 1024 threads.
// ---------------------------------------------------------------------------
__global__ void k_scan() {
    __shared__ unsigned int sh[NBUCK];
    __shared__ unsigned int part[1024];
    __shared__ int sT;
    const int b = blockIdx.x;
    const int t = threadIdx.x;

    for (int i = t; i < NBUCK; i += 1024) sh[i] = g_hist[b * NBUCK + i];
    if (t == 0) sT = -1;
    __syncthreads();

    const unsigned int p = sh[4 * t] + sh[4 * t + 1] + sh[4 * t + 2] + sh[4 * t + 3];
    part[t] = p;
    __syncthreads();

    // inclusive suffix scan over 1024 partials
    for (int off = 1; off < 1024; off <<= 1) {
        unsigned int v = 0;
        if (t + off < 1024) v = part[t + off];
        __syncthreads();
        part[t] += v;
        __syncthreads();
    }

    // largest bucket j (within this thread's 4) whose suffix-count >= TOPK
    unsigned int acc = part[t] - p;  // exclusive: sum over buckets of threads > t
    for (int j = 3; j >= 0; j--) {
        acc += sh[4 * t + j];
        if (acc >= (unsigned)TOPK_) { atomicMax(&sT, 4 * t + j); break; }
    }
    __syncthreads();
    if (t == 0) g_thresh[b] = (unsigned int)sT;
}

// ---------------------------------------------------------------------------
// Kernel 3: compaction — keep everything with bucket >= threshold as packed
// 64-bit key: (ordered_score << 32) | (0xFFFFFFFF - idx).
// Descending key order == (score desc, index asc) == jax.lax.top_k order.
// ---------------------------------------------------------------------------
__device__ __forceinline__ void emit_cand(int b, unsigned int T, float x, int idx) {
    const unsigned int o = ordf(x);
    if ((o >> 20) >= T) {
        const int pos = atomicAdd(&g_count[b], 1);
        if (pos < CAP)
            g_cand[b * CAP + pos] =
                ((unsigned long long)o << 32) | (unsigned long long)(0xFFFFFFFFu - (unsigned int)idx);
    }
}

__global__ void k_compact(const float* __restrict__ preds) {
    const int b = blockIdx.y;
    const unsigned int T = g_thresh[b];
    const float4* sc = (const float4*)(preds + (size_t)b * 3 * HW_);
    const int base = blockIdx.x * 4096;
    for (int i = threadIdx.x; i < 4096; i += 256) {
        const int i4 = base + i;
        const float4 v = sc[i4];
        const int idx0 = i4 * 4;
        emit_cand(b, T, v.x, idx0 + 0);
        emit_cand(b, T, v.y, idx0 + 1);
        emit_cand(b, T, v.z, idx0 + 2);
        emit_cand(b, T, v.w, idx0 + 3);
    }
}

// ---------------------------------------------------------------------------
// Kernel 4: exact rank selection + emit. One block (1024 thr) per image.
// M <= 4096 keys in shared; rank(k) = #{keys > k}; rank < 1000 -> output slot.
// Keys are unique (index embedded) so ranks are a permutation -> every output
// slot written exactly once. NMS is identity (IoU<=1, thr=1.0, strict >).
// ---------------------------------------------------------------------------
__global__ void k_select(const float* __restrict__ preds, float* __restrict__ out) {
    __shared__ unsigned long long keys[CAP];
    const int b = blockIdx.x;
    const int t = threadIdx.x;
    const int M = min(g_count[b], CAP);

    for (int i = t; i < M; i += 1024) keys[i] = g_cand[b * CAP + i];
    __syncthreads();

    const float* ph = preds + (size_t)b * 3 * HW_ + HW_;
    const float* pw = ph + HW_;
    float* boxes  = out;                              // [B, K, 4]
    float* scores = out + (size_t)B_ * TOPK_ * 4;     // [B, K]
    float* keep   = scores + (size_t)B_ * TOPK_;      // [B, K]

    for (int c = t; c < M; c += 1024) {
        const unsigned long long k = keys[c];
        int rank = 0;
        for (int j = 0; j < M; j++) rank += (keys[j] > k);
        if (rank < TOPK_) {
            const unsigned int o = (unsigned int)(k >> 32);
            const unsigned int u = (o & 0x80000000u) ? (o ^ 0x80000000u) : ~o;
            const float score = __uint_as_float(u);
            const unsigned int idx = 0xFFFFFFFFu - (unsigned int)(k & 0xFFFFFFFFull);

            const float h = fmaxf(ph[idx], 1e-6f) * (float)H_;
            const float w = fmaxf(pw[idx], 1e-6f) * (float)W_;
            const float cx = (float)(idx % W_);
            const float cy = (float)(idx / W_);

            float* bx = boxes + ((size_t)b * TOPK_ + rank) * 4;
            bx[0] = cx - 0.5f * w;
            bx[1] = cy - 0.5f * h;
            bx[2] = cx + 0.5f * w;
            bx[3] = cy + 0.5f * h;
            scores[b * TOPK_ + rank] = score;
            keep[b * TOPK_ + rank]   = 1.0f;
        }
    }
}

// ---------------------------------------------------------------------------
extern "C" void kernel_launch(void* const* d_in, const int* in_sizes, int n_in,
                              void* d_out, int out_size) {
    const float* preds = (const float*)d_in[0];
    float* out = (float*)d_out;

    k_zero<<<(B_ * NBUCK + 255) / 256, 256>>>();

    dim3 g(HW_ / (4096 * 4), B_);   // (25, 32)
    k_hist<<<g, 256>>>(preds);
    k_scan<<<B_, 1024>>>();
    k_compact<<<g, 256>>>(preds);
    k_select<<<B_, 1024>>>(preds, out);
}

// round 2
// speedup vs baseline: 1.3071x; 1.3071x over previous
#include <cuda_runtime.h>
#include <stdint.h>

// preds: [32, 3, 640, 640] fp32
#define B_    32
#define H_    640
#define W_    640
#define HW_   (H_ * W_)          // 409600
#define TOPK_ 1000
#define NBUCK 4096
#define CAP   4096               // candidate cap per image (keys)
#define TG    2.6f               // static fast-path score threshold (p~0.0047 -> ~1900/img)

// Scratch (device globals; no allocations allowed)
__device__ unsigned long long g_cand[B_ * CAP];
__device__ unsigned long long g_surv[B_ * CAP];
__device__ int                g_count[B_];
__device__ int                g_scount[B_];
__device__ int                g_need[B_];
__device__ unsigned int       g_hist[B_ * NBUCK];
__device__ int                g_fbthresh[B_];

// Order-preserving bijection float -> uint (monotone increasing)
__device__ __forceinline__ unsigned int ordf(float x) {
    unsigned int u = __float_as_uint(x);
    return (u & 0x80000000u) ? ~u : (u | 0x80000000u);
}

// ---------------------------------------------------------------------------
// Kernel 0: zero scratch every launch (graph replays).
// ---------------------------------------------------------------------------
__global__ void k_zero() {
    int i = blockIdx.x * blockDim.x + threadIdx.x;
    if (i < B_ * NBUCK) g_hist[i] = 0u;
    if (i < B_) { g_count[i] = 0; g_scount[i] = 0; g_need[i] = 0; }
}

// ---------------------------------------------------------------------------
// Kernel 1: single streaming pass — compact all scores >= TG into 64-bit keys
//   key = (ordered_score << 32) | (0xFFFFFFFF - idx)
// Descending key order == (score desc, index asc) == jax.lax.top_k order.
// grid (25, 32) x 512 threads; each thread: 8 independent float4 loads (MLP=8).
// ---------------------------------------------------------------------------
__global__ void k_pass1(const float* __restrict__ preds) {
    const int b = blockIdx.y;
    const float4* sc = (const float4*)(preds + (size_t)b * 3 * HW_);
    const int tid = blockIdx.x * 512 + threadIdx.x;   // 0..12799

    float4 v[8];
#pragma unroll
    for (int j = 0; j < 8; j++) v[j] = sc[tid + j * 12800];

#pragma unroll
    for (int j = 0; j < 8; j++) {
        const int i4 = tid + j * 12800;
        const float f0 = v[j].x, f1 = v[j].y, f2 = v[j].z, f3 = v[j].w;
#pragma unroll
        for (int k = 0; k < 4; k++) {
            const float f = (k == 0) ? f0 : (k == 1) ? f1 : (k == 2) ? f2 : f3;
            if (f >= TG) {
                const int pos = atomicAdd(&g_count[b], 1);
                if (pos < CAP) {
                    const unsigned int o = ordf(f);
                    const unsigned int idx = (unsigned int)(i4 * 4 + k);
                    g_cand[b * CAP + pos] =
                        ((unsigned long long)o << 32) | (unsigned long long)(0xFFFFFFFFu - idx);
                }
            }
        }
    }
}

// ---------------------------------------------------------------------------
// Kernel 2: check whether the fast path produced a valid candidate superset.
// ---------------------------------------------------------------------------
__global__ void k_check() {
    const int b = threadIdx.x;
    if (b < B_) {
        const int c = g_count[b];
        g_need[b] = (c < TOPK_) || (c > CAP);
    }
}

// ---------------------------------------------------------------------------
// Fallback kernels (early-exit when fast path succeeded): exact radix-bucket
// threshold over the full score channel, then recompaction.
// ---------------------------------------------------------------------------
__global__ void k_fb_hist(const float* __restrict__ preds) {
    const int b = blockIdx.y;
    if (!g_need[b]) return;
    __shared__ unsigned int sh[NBUCK];
    for (int i = threadIdx.x; i < NBUCK; i += 256) sh[i] = 0u;
    __syncthreads();

    const float4* sc = (const float4*)(preds + (size_t)b * 3 * HW_);
    const int base = blockIdx.x * 4096;
    for (int i = threadIdx.x; i < 4096; i += 256) {
        float4 v = sc[base + i];
        atomicAdd(&sh[ordf(v.x) >> 20], 1u);
        atomicAdd(&sh[ordf(v.y) >> 20], 1u);
        atomicAdd(&sh[ordf(v.z) >> 20], 1u);
        atomicAdd(&sh[ordf(v.w) >> 20], 1u);
    }
    __syncthreads();
    unsigned int* gh = g_hist + b * NBUCK;
    for (int i = threadIdx.x; i < NBUCK; i += 256)
        if (sh[i]) atomicAdd(&gh[i], sh[i]);
}

__global__ void k_fb_scan() {
    const int b = blockIdx.x;
    if (!g_need[b]) return;
    __shared__ unsigned int sh[NBUCK];
    __shared__ unsigned int part[1024];
    __shared__ int sT;
    const int t = threadIdx.x;

    for (int i = t; i < NBUCK; i += 1024) sh[i] = g_hist[b * NBUCK + i];
    if (t == 0) sT = 0;
    __syncthreads();

    const unsigned int p = sh[4 * t] + sh[4 * t + 1] + sh[4 * t + 2] + sh[4 * t + 3];
    part[t] = p;
    __syncthreads();
    for (int off = 1; off < 1024; off <<= 1) {
        unsigned int v = 0;
        if (t + off < 1024) v = part[t + off];
        __syncthreads();
        part[t] += v;
        __syncthreads();
    }
    unsigned int acc = part[t] - p;
    for (int j = 3; j >= 0; j--) {
        acc += sh[4 * t + j];
        if (acc >= (unsigned)TOPK_) { atomicMax(&sT, 4 * t + j); break; }
    }
    __syncthreads();
    if (t == 0) { g_fbthresh[b] = sT; g_count[b] = 0; }
}

__global__ void k_fb_compact(const float* __restrict__ preds) {
    const int b = blockIdx.y;
    if (!g_need[b]) return;
    const unsigned int T = (unsigned int)g_fbthresh[b];
    const float4* sc = (const float4*)(preds + (size_t)b * 3 * HW_);
    const int base = blockIdx.x * 4096;
    for (int i = threadIdx.x; i < 4096; i += 256) {
        const int i4 = base + i;
        const float4 v = sc[i4];
        const float f[4] = {v.x, v.y, v.z, v.w};
#pragma unroll
        for (int k = 0; k < 4; k++) {
            const unsigned int o = ordf(f[k]);
            if ((o >> 20) >= T) {
                const int pos = atomicAdd(&g_count[b], 1);
                if (pos < CAP) {
                    const unsigned int idx = (unsigned int)(i4 * 4 + k);
                    g_cand[b * CAP + pos] =
                        ((unsigned long long)o << 32) | (unsigned long long)(0xFFFFFFFFu - idx);
                }
            }
        }
    }
}

// ---------------------------------------------------------------------------
// Kernel 3: per-image narrowing. Finds the exact bucket threshold (on a
// monotone min/max-normalized 12-bit bucketing of the ordered score) such
// that >= TOPK candidates survive, and compacts the survivors.
// One block of 1024 threads per image.
// ---------------------------------------------------------------------------
__global__ void k_thresh() {
    __shared__ unsigned int hi[CAP];           // 16 KB
    __shared__ unsigned int hist[NBUCK];       // 16 KB
    __shared__ unsigned int part[1024];        // 4 KB
    __shared__ unsigned int rmin[32], rmax[32];
    __shared__ unsigned int s_min, s_shift;
    __shared__ int sT, s_pos;

    const int b = blockIdx.x;
    const int t = threadIdx.x;
    const int M = min(g_count[b], CAP);

    // load high words; block min/max
    unsigned int lmin = 0xFFFFFFFFu, lmax = 0u;
    for (int i = t; i < M; i += 1024) {
        const unsigned int h = (unsigned int)(g_cand[b * CAP + i] >> 32);
        hi[i] = h;
        lmin = min(lmin, h);
        lmax = max(lmax, h);
    }
#pragma unroll
    for (int off = 16; off > 0; off >>= 1) {
        lmin = min(lmin, __shfl_down_sync(0xFFFFFFFFu, lmin, off));
        lmax = max(lmax, __shfl_down_sync(0xFFFFFFFFu, lmax, off));
    }
    if ((t & 31) == 0) { rmin[t >> 5] = lmin; rmax[t >> 5] = lmax; }
    for (int i = t; i < NBUCK; i += 1024) hist[i] = 0u;
    if (t == 0) { sT = 0; s_pos = 0; }
    __syncthreads();
    if (t == 0) {
        unsigned int mn = 0xFFFFFFFFu, mx = 0u;
        for (int i = 0; i < 32; i++) { mn = min(mn, rmin[i]); mx = max(mx, rmax[i]); }
        const unsigned int range = mx - mn;
        unsigned int shift = 0;
        const int bits = 32 - __clz(range | 1u);
        if (bits > 12) shift = bits - 12;
        s_min = mn; s_shift = shift;
    }
    __syncthreads();
    const unsigned int mn = s_min, shift = s_shift;

    // histogram on monotone buckets
    for (int i = t; i < M; i += 1024)
        atomicAdd(&hist[(hi[i] - mn) >> shift], 1u);
    __syncthreads();

    // inclusive suffix scan over 4096 buckets (4 per thread)
    const unsigned int p = hist[4 * t] + hist[4 * t + 1] + hist[4 * t + 2] + hist[4 * t + 3];
    part[t] = p;
    __syncthreads();
    for (int off = 1; off < 1024; off <<= 1) {
        unsigned int v = 0;
        if (t + off < 1024) v = part[t + off];
        __syncthreads();
        part[t] += v;
        __syncthreads();
    }
    unsigned int acc = part[t] - p;
    for (int j = 3; j >= 0; j--) {
        acc += hist[4 * t + j];
        if (acc >= (unsigned)TOPK_) { atomicMax(&sT, 4 * t + j); break; }
    }
    __syncthreads();
    const int T2 = sT;

    // compact survivors (bucket >= T2); order irrelevant (ranks computed later)
    for (int i = t; i < M; i += 1024) {
        if ((int)((hi[i] - mn) >> shift) >= T2) {
            const int pos = atomicAdd(&s_pos, 1);
            if (pos < CAP) g_surv[b * CAP + pos] = g_cand[b * CAP + i];
        }
    }
    __syncthreads();
    if (t == 0) g_scount[b] = min(s_pos, CAP);
}

// ---------------------------------------------------------------------------
// Kernel 4: rank survivors against survivors (exact global rank, since all
// non-survivors are strictly smaller) and emit boxes/scores/keep.
// grid (8, 32) x 256 threads; each block loads all survivor keys to shared.
// ---------------------------------------------------------------------------
__global__ void k_rank(const float* __restrict__ preds, float* __restrict__ out) {
    __shared__ unsigned long long keys[CAP];   // 32 KB
    const int b = blockIdx.y;
    const int Ms = g_scount[b];
    const int t = threadIdx.x;

    for (int i = t; i < Ms; i += 256) keys[i] = g_surv[b * CAP + i];
    __syncthreads();

    const float* ph = preds + (size_t)b * 3 * HW_ + HW_;
    const float* pw = ph + HW_;
    float* boxes  = out;                              // [B, K, 4]
    float* scores = out + (size_t)B_ * TOPK_ * 4;     // [B, K]
    float* keep   = scores + (size_t)B_ * TOPK_;      // [B, K]

    for (int c = blockIdx.x * 256 + t; c < Ms; c += 8 * 256) {
        const unsigned long long k = keys[c];
        int rank = 0;
#pragma unroll 4
        for (int j = 0; j < Ms; j++) rank += (keys[j] > k);
        if (rank < TOPK_) {
            const unsigned int o = (unsigned int)(k >> 32);
            const unsigned int u = (o & 0x80000000u) ? (o ^ 0x80000000u) : ~o;
            const float score = __uint_as_float(u);
            const unsigned int idx = 0xFFFFFFFFu - (unsigned int)(k & 0xFFFFFFFFull);

            const float h = fmaxf(ph[idx], 1e-6f) * (float)H_;
            const float w = fmaxf(pw[idx], 1e-6f) * (float)W_;
            const float cx = (float)(idx % W_);
            const float cy = (float)(idx / W_);

            float* bx = boxes + ((size_t)b * TOPK_ + rank) * 4;
            bx[0] = cx - 0.5f * w;
            bx[1] = cy - 0.5f * h;
            bx[2] = cx + 0.5f * w;
            bx[3] = cy + 0.5f * h;
            scores[b * TOPK_ + rank] = score;
            keep[b * TOPK_ + rank]   = 1.0f;
        }
    }
}

// ---------------------------------------------------------------------------
extern "C" void kernel_launch(void* const* d_in, const int* in_sizes, int n_in,
                              void* d_out, int out_size) {
    const float* preds = (const float*)d_in[0];
    float* out = (float*)d_out;

    k_zero<<<(B_ * NBUCK + 255) / 256, 256>>>();

    dim3 gp(25, B_);
    k_pass1<<<gp, 512>>>(preds);
    k_check<<<1, 32>>>();

    dim3 gf(25, B_);
    k_fb_hist<<<gf, 256>>>(preds);
    k_fb_scan<<<B_, 1024>>>();
    k_fb_compact<<<gf, 256>>>(preds);

    k_thresh<<<B_, 1024>>>();
    dim3 gr(8, B_);
    k_rank<<<gr, 256>>>(preds, out);
}